// round 2
// baseline (speedup 1.0000x reference)
#include <cuda_runtime.h>
#include <stdint.h>

#define BN      16384
#define IN_DIM  256
#define HID     128
#define NCLS    8
#define T_STEPS 64
#define BETA    0.9f

// Scratch (no cudaMalloc allowed)
__device__ float g_cur1[BN * HID];          // 8 MB   cur1 = x@W1^T + b1
__device__ uint4 g_masks[T_STEPS * BN];     // 16 MB  [t][sample] 128-bit spike masks

// ---------------------------------------------------------------------------
// K1: cur1[s][h] = sum_k x[s][k] * W1[h][k] + b1[h]
// CTA tile: 64 samples x 128 hid, K-chunks of 32. 256 threads, 8x4 per thread.
// ---------------------------------------------------------------------------
__global__ __launch_bounds__(256) void k1_fc1(const float* __restrict__ x,
                                              const float* __restrict__ W1,
                                              const float* __restrict__ b1)
{
    __shared__ float xs[32 * 68];    // [k][s], row stride 68 floats (16B-aligned rows)
    __shared__ float ws[32 * 132];   // [k][h], row stride 132 floats

    const int tid = threadIdx.x;
    const int bs  = blockIdx.x * 64;       // sample base
    const int c   = tid & 7;               // sample group (8 samples each)
    const int r   = tid >> 3;              // hid group (4 hid each), 0..31

    float acc[4][8];
#pragma unroll
    for (int i = 0; i < 4; i++)
#pragma unroll
        for (int j = 0; j < 8; j++) acc[i][j] = 0.0f;

    for (int kc = 0; kc < IN_DIM; kc += 32) {
        // load x tile: 64 samples x 32 k  (512 float4s, 2 per thread)
#pragma unroll
        for (int i = 0; i < 2; i++) {
            int f  = i * 256 + tid;
            int s  = f >> 3;
            int k4 = f & 7;
            float4 v = *(const float4*)&x[(bs + s) * IN_DIM + kc + k4 * 4];
            xs[(k4 * 4 + 0) * 68 + s] = v.x;
            xs[(k4 * 4 + 1) * 68 + s] = v.y;
            xs[(k4 * 4 + 2) * 68 + s] = v.z;
            xs[(k4 * 4 + 3) * 68 + s] = v.w;
        }
        // load W1 tile: 128 hid x 32 k (1024 float4s, 4 per thread)
#pragma unroll
        for (int i = 0; i < 4; i++) {
            int f  = i * 256 + tid;
            int h  = f >> 3;
            int k4 = f & 7;
            float4 v = *(const float4*)&W1[h * IN_DIM + kc + k4 * 4];
            ws[(k4 * 4 + 0) * 132 + h] = v.x;
            ws[(k4 * 4 + 1) * 132 + h] = v.y;
            ws[(k4 * 4 + 2) * 132 + h] = v.z;
            ws[(k4 * 4 + 3) * 132 + h] = v.w;
        }
        __syncthreads();

#pragma unroll 8
        for (int k = 0; k < 32; k++) {
            float4 a0 = *(const float4*)&xs[k * 68 + c * 8];
            float4 a1 = *(const float4*)&xs[k * 68 + c * 8 + 4];
            float4 bv = *(const float4*)&ws[k * 132 + r * 4];
            float a[8] = {a0.x, a0.y, a0.z, a0.w, a1.x, a1.y, a1.z, a1.w};
            float bb[4] = {bv.x, bv.y, bv.z, bv.w};
#pragma unroll
            for (int i = 0; i < 4; i++)
#pragma unroll
                for (int j = 0; j < 8; j++)
                    acc[i][j] = fmaf(bb[i], a[j], acc[i][j]);
        }
        __syncthreads();
    }

    // epilogue: += b1, store float4 along hid
    float4 b1v = *(const float4*)&b1[r * 4];
#pragma unroll
    for (int j = 0; j < 8; j++) {
        int s = bs + c * 8 + j;
        float4 o;
        o.x = acc[0][j] + b1v.x;
        o.y = acc[1][j] + b1v.y;
        o.z = acc[2][j] + b1v.z;
        o.w = acc[3][j] + b1v.w;
        *(float4*)&g_cur1[s * HID + r * 4] = o;
    }
}

// ---------------------------------------------------------------------------
// K2: layer-1 LIF recurrence + spike mask packing.
// Warp = one 32-hid group x 4 samples. Block = 8 warps = 8 samples (4 groups).
// ---------------------------------------------------------------------------
__global__ __launch_bounds__(256) void k2_lif1()
{
    __shared__ uint32_t sm[T_STEPS][8][4];   // [t][sampleLocal][group] = 8 KB

    const int tid  = threadIdx.x;
    const int w    = tid >> 5;
    const int lane = tid & 31;
    const int g    = w & 3;      // hid group
    const int q    = w >> 2;     // sample quad 0/1
    const int sb   = blockIdx.x * 8 + q * 4;
    const int h    = g * 32 + lane;

    float cur[4], mem[4];
#pragma unroll
    for (int j = 0; j < 4; j++) {
        cur[j] = g_cur1[(sb + j) * HID + h];
        mem[j] = 0.0f;
    }

    for (int t = 0; t < T_STEPS; t++) {
#pragma unroll
        for (int j = 0; j < 4; j++) {
            float m  = mem[j];
            float rf = (m > 1.0f) ? 1.0f : 0.0f;            // reset from incoming mem
            m = fmaf(BETA, m, cur[j]) - rf;                 // (beta*mem + cur) - reset
            mem[j] = m;
            unsigned bal = __ballot_sync(0xffffffffu, m > 1.0f);
            if (lane == 0) sm[t][q * 4 + j][g] = bal;
        }
    }
    __syncthreads();

    // coalesced write-out: [t][B] planes of uint4
    for (int idx = tid; idx < T_STEPS * 8; idx += 256) {
        int t  = idx >> 3;
        int sl = idx & 7;
        uint4 v = *(const uint4*)&sm[t][sl][0];
        g_masks[t * BN + blockIdx.x * 8 + sl] = v;
    }
}

// ---------------------------------------------------------------------------
// K3: layer-2 via byte-pattern LUT + LIF recurrence + spike accumulation.
// LUT[chunk][byte][cls] = sum of W2[cls][chunk*8 + j] over set bits j.
// 16*256*8 floats = 128 KB dynamic smem (1 CTA/SM). 128 blocks x 128 threads.
// ---------------------------------------------------------------------------
__global__ __launch_bounds__(128) void k3_lif2(const float* __restrict__ W2,
                                               const float* __restrict__ b2,
                                               float* __restrict__ out)
{
    extern __shared__ float lut[];   // [16][256][8]
    const int tid = threadIdx.x;

    for (int e = tid; e < 16 * 256; e += blockDim.x) {
        int chunk = e >> 8;
        int byte  = e & 255;
        float v[8];
#pragma unroll
        for (int cc = 0; cc < 8; cc++) v[cc] = 0.0f;
#pragma unroll
        for (int j = 0; j < 8; j++) {
            if ((byte >> j) & 1) {
#pragma unroll
                for (int cc = 0; cc < 8; cc++)
                    v[cc] += W2[cc * HID + chunk * 8 + j];
            }
        }
#pragma unroll
        for (int cc = 0; cc < 8; cc++) lut[e * 8 + cc] = v[cc];
    }
    __syncthreads();

    const int s = blockIdx.x * 128 + tid;   // one sample per thread

    float b2r[8];
#pragma unroll
    for (int cc = 0; cc < 8; cc++) b2r[cc] = __ldg(&b2[cc]);

    float mem[8], acc[8];
#pragma unroll
    for (int cc = 0; cc < 8; cc++) { mem[cc] = 0.0f; acc[cc] = 0.0f; }

    for (int t = 0; t < T_STEPS; t++) {
        uint4 m = g_masks[t * BN + s];
        uint32_t wv[4] = {m.x, m.y, m.z, m.w};

        float4 A  = make_float4(b2r[0], b2r[1], b2r[2], b2r[3]);
        float4 Bv = make_float4(b2r[4], b2r[5], b2r[6], b2r[7]);
#pragma unroll
        for (int g = 0; g < 4; g++) {
            uint32_t wg = wv[g];
#pragma unroll
            for (int j = 0; j < 4; j++) {
                int idx = (((g * 4 + j) << 8) + ((wg >> (8 * j)) & 255)) * 8;
                float4 p0 = *(const float4*)&lut[idx];
                float4 p1 = *(const float4*)&lut[idx + 4];
                A.x += p0.x;  A.y += p0.y;  A.z += p0.z;  A.w += p0.w;
                Bv.x += p1.x; Bv.y += p1.y; Bv.z += p1.z; Bv.w += p1.w;
            }
        }
        float cur[8] = {A.x, A.y, A.z, A.w, Bv.x, Bv.y, Bv.z, Bv.w};
#pragma unroll
        for (int cc = 0; cc < 8; cc++) {
            float mm = mem[cc];
            float rf = (mm > 1.0f) ? 1.0f : 0.0f;
            mm = fmaf(BETA, mm, cur[cc]) - rf;
            mem[cc] = mm;
            acc[cc] += (mm > 1.0f) ? 1.0f : 0.0f;
        }
    }

    float4 o0 = make_float4(acc[0], acc[1], acc[2], acc[3]);
    float4 o1 = make_float4(acc[4], acc[5], acc[6], acc[7]);
    *(float4*)&out[s * 8]     = o0;
    *(float4*)&out[s * 8 + 4] = o1;
}

// ---------------------------------------------------------------------------
extern "C" void kernel_launch(void* const* d_in, const int* in_sizes, int n_in,
                              void* d_out, int out_size)
{
    const float* x  = (const float*)d_in[0];
    const float* W1 = (const float*)d_in[1];
    const float* b1 = (const float*)d_in[2];
    const float* W2 = (const float*)d_in[3];
    const float* b2 = (const float*)d_in[4];
    float* out = (float*)d_out;

    k1_fc1<<<BN / 64, 256>>>(x, W1, b1);
    k2_lif1<<<BN / 8, 256>>>();

    cudaFuncSetAttribute(k3_lif2, cudaFuncAttributeMaxDynamicSharedMemorySize, 131072);
    k3_lif2<<<BN / 128, 128, 131072>>>(W2, b2, out);
}